// round 1
// baseline (speedup 1.0000x reference)
#include <cuda_runtime.h>

// AlmostFairKCRPSLoss: target (1,6,2,192,288) f32, pred (16,6,2,192,288) f32.
// Per location s: skill = mean_i |p_i - t|, spread = sum_{i,j}|p_i-p_j| / (2*m*(m-1)),
// ALPHA=1 -> epsilon=0 -> crps = skill - spread. Output = mean over locations (scalar f32).
//
// Strategy: one thread per location. 16 coalesced member streams (stride NLOC).
// Pairwise sum via Batcher sort (63 CAS) + rank-weighted sum: sum_{i<j}|p_i-p_j|
// = sum_k (2k-15)*p_sorted[k]. Block-reduce, atomicAdd(double) scratch, finalize.

static constexpr int M_ENS = 16;
static constexpr int NLOC = 6 * 2 * 192 * 288;  // 663552
static constexpr int THREADS = 256;
static constexpr int BLOCKS = (NLOC + THREADS - 1) / THREADS;  // 2592

__device__ double g_acc;

__global__ void crps_init_kernel() { g_acc = 0.0; }

#define CAS(a, b)                          \
    do {                                   \
        float _lo = fminf(p[a], p[b]);     \
        float _hi = fmaxf(p[a], p[b]);     \
        p[a] = _lo;                        \
        p[b] = _hi;                        \
    } while (0)

__global__ __launch_bounds__(THREADS) void crps_main_kernel(
    const float* __restrict__ target, const float* __restrict__ pred) {
    const int s = blockIdx.x * blockDim.x + threadIdx.x;

    float crps = 0.0f;
    if (s < NLOC) {
        const float t = __ldg(target + s);
        float p[M_ENS];
#pragma unroll
        for (int i = 0; i < M_ENS; i++) {
            p[i] = __ldg(pred + (long long)i * NLOC + s);
        }

        // skill = sum_i |p_i - t|   (order-independent, do before sorting)
        float skill = 0.0f;
#pragma unroll
        for (int i = 0; i < M_ENS; i++) skill += fabsf(p[i] - t);

        // Batcher merge-exchange sorting network for 16 elements (63 comparators)
        // p = 8
        CAS(0, 8);  CAS(1, 9);  CAS(2, 10); CAS(3, 11);
        CAS(4, 12); CAS(5, 13); CAS(6, 14); CAS(7, 15);
        // p = 4
        CAS(0, 4);  CAS(1, 5);  CAS(2, 6);  CAS(3, 7);
        CAS(8, 12); CAS(9, 13); CAS(10, 14); CAS(11, 15);
        CAS(4, 8);  CAS(5, 9);  CAS(6, 10); CAS(7, 11);
        // p = 2
        CAS(0, 2);  CAS(1, 3);  CAS(4, 6);  CAS(5, 7);
        CAS(8, 10); CAS(9, 11); CAS(12, 14); CAS(13, 15);
        CAS(2, 8);  CAS(3, 9);  CAS(6, 12); CAS(7, 13);
        CAS(2, 4);  CAS(3, 5);  CAS(6, 8);  CAS(7, 9);  CAS(10, 12); CAS(11, 13);
        // p = 1
        CAS(0, 1);  CAS(2, 3);  CAS(4, 5);  CAS(6, 7);
        CAS(8, 9);  CAS(10, 11); CAS(12, 13); CAS(14, 15);
        CAS(1, 8);  CAS(3, 10); CAS(5, 12); CAS(7, 14);
        CAS(1, 4);  CAS(3, 6);  CAS(5, 8);  CAS(7, 10); CAS(9, 12); CAS(11, 14);
        CAS(1, 2);  CAS(3, 4);  CAS(5, 6);  CAS(7, 8);
        CAS(9, 10); CAS(11, 12); CAS(13, 14);

        // sum_{i<j} |p_i - p_j| = sum_k (2k-15) * p_sorted[k]
        float ws = 0.0f;
#pragma unroll
        for (int k = 0; k < M_ENS; k++) {
            ws = fmaf((float)(2 * k - 15), p[k], ws);
        }

        // spread (both orderings, /(2*m*(m-1))) = 2*ws / 480 = ws / 240
        crps = skill * (1.0f / 16.0f) - ws * (1.0f / 240.0f);
    }

    // ---- block reduction ----
    __shared__ float warp_sums[THREADS / 32];
    float v = crps;
#pragma unroll
    for (int o = 16; o > 0; o >>= 1) v += __shfl_xor_sync(0xFFFFFFFFu, v, o);
    const int lane = threadIdx.x & 31;
    const int wid = threadIdx.x >> 5;
    if (lane == 0) warp_sums[wid] = v;
    __syncthreads();
    if (wid == 0) {
        float bv = (lane < (THREADS / 32)) ? warp_sums[lane] : 0.0f;
#pragma unroll
        for (int o = 4; o > 0; o >>= 1) bv += __shfl_xor_sync(0xFFFFFFFFu, bv, o);
        if (lane == 0) atomicAdd(&g_acc, (double)bv);
    }
}

__global__ void crps_finalize_kernel(float* __restrict__ out) {
    out[0] = (float)(g_acc / (double)NLOC);
}

extern "C" void kernel_launch(void* const* d_in, const int* in_sizes, int n_in,
                              void* d_out, int out_size) {
    const float* a = (const float*)d_in[0];
    const float* b = (const float*)d_in[1];
    // target is the smaller tensor (NLOC), pred the larger (16*NLOC)
    const float* target = a;
    const float* pred = b;
    if (n_in >= 2 && in_sizes[0] > in_sizes[1]) {
        target = b;
        pred = a;
    }
    crps_init_kernel<<<1, 1>>>();
    crps_main_kernel<<<BLOCKS, THREADS>>>(target, pred);
    crps_finalize_kernel<<<1, 1>>>((float*)d_out);
}

// round 2
// speedup vs baseline: 1.0021x; 1.0021x over previous
#include <cuda_runtime.h>

// AlmostFairKCRPSLoss, single-launch version.
// target (1,6,2,192,288) f32, pred (16,...) f32, out = scalar mean CRPS.
// crps(s) = mean_i|p_i - t| - sum_{i<j}|p_i-p_j| / 240   (ALPHA=1, m=16)
// sum_{i<j}|p_i-p_j| computed via 16-input Batcher sort + rank weights (2k-15).
//
// One kernel launch: float4 (4 locations/thread), per-block partials in a
// __device__ array (no init kernel), last-block-done reduction (no finalize
// kernel). Ticket counter is reset by the last block -> graph-replay safe.

static constexpr int M_ENS = 16;
static constexpr int NLOC = 6 * 2 * 192 * 288;  // 663552
static constexpr int NQ = NLOC / 4;             // 165888 float4 "quads"
static constexpr int THREADS = 256;
static constexpr int BLOCKS = NQ / THREADS;     // 648 (exact)

__device__ float g_part[BLOCKS];
__device__ unsigned int g_ticket = 0;  // always 0 between launches (last block resets)

#define CAS(a, b)                          \
    do {                                   \
        float _lo = fminf(p[a], p[b]);     \
        float _hi = fmaxf(p[a], p[b]);     \
        p[a] = _lo;                        \
        p[b] = _hi;                        \
    } while (0)

__device__ __forceinline__ float crps_one(const float4* v4, int c, float t) {
    float p[M_ENS];
#pragma unroll
    for (int i = 0; i < M_ENS; i++) {
        const float* f = (const float*)(v4 + i);
        p[i] = f[c];
    }

    float skill = 0.0f;
#pragma unroll
    for (int i = 0; i < M_ENS; i++) skill += fabsf(p[i] - t);

    // Batcher merge-exchange network, 16 inputs, 63 comparators
    CAS(0, 8);  CAS(1, 9);  CAS(2, 10); CAS(3, 11);
    CAS(4, 12); CAS(5, 13); CAS(6, 14); CAS(7, 15);
    CAS(0, 4);  CAS(1, 5);  CAS(2, 6);  CAS(3, 7);
    CAS(8, 12); CAS(9, 13); CAS(10, 14); CAS(11, 15);
    CAS(4, 8);  CAS(5, 9);  CAS(6, 10); CAS(7, 11);
    CAS(0, 2);  CAS(1, 3);  CAS(4, 6);  CAS(5, 7);
    CAS(8, 10); CAS(9, 11); CAS(12, 14); CAS(13, 15);
    CAS(2, 8);  CAS(3, 9);  CAS(6, 12); CAS(7, 13);
    CAS(2, 4);  CAS(3, 5);  CAS(6, 8);  CAS(7, 9);  CAS(10, 12); CAS(11, 13);
    CAS(0, 1);  CAS(2, 3);  CAS(4, 5);  CAS(6, 7);
    CAS(8, 9);  CAS(10, 11); CAS(12, 13); CAS(14, 15);
    CAS(1, 8);  CAS(3, 10); CAS(5, 12); CAS(7, 14);
    CAS(1, 4);  CAS(3, 6);  CAS(5, 8);  CAS(7, 10); CAS(9, 12); CAS(11, 14);
    CAS(1, 2);  CAS(3, 4);  CAS(5, 6);  CAS(7, 8);
    CAS(9, 10); CAS(11, 12); CAS(13, 14);

    float ws = 0.0f;
#pragma unroll
    for (int k = 0; k < M_ENS; k++) ws = fmaf((float)(2 * k - 15), p[k], ws);

    return skill * (1.0f / 16.0f) - ws * (1.0f / 240.0f);
}

__global__ __launch_bounds__(THREADS) void crps_kernel(
    const float4* __restrict__ target4, const float4* __restrict__ pred4,
    float* __restrict__ out) {
    const int q = blockIdx.x * THREADS + threadIdx.x;  // quad index, always < NQ

    // 16 coalesced 128-bit member loads (front-batched -> MLP=16)
    float4 v4[M_ENS];
#pragma unroll
    for (int i = 0; i < M_ENS; i++) v4[i] = pred4[(long long)i * NQ + q];
    const float4 t4 = target4[q];

    float crps = crps_one(v4, 0, t4.x) + crps_one(v4, 1, t4.y) +
                 crps_one(v4, 2, t4.z) + crps_one(v4, 3, t4.w);

    // ---- block reduction ----
    __shared__ float warp_sums[THREADS / 32];
    float v = crps;
#pragma unroll
    for (int o = 16; o > 0; o >>= 1) v += __shfl_xor_sync(0xFFFFFFFFu, v, o);
    const int lane = threadIdx.x & 31;
    const int wid = threadIdx.x >> 5;
    if (lane == 0) warp_sums[wid] = v;
    __syncthreads();

    __shared__ bool s_last;
    if (wid == 0) {
        float bv = (lane < (THREADS / 32)) ? warp_sums[lane] : 0.0f;
#pragma unroll
        for (int o = 4; o > 0; o >>= 1) bv += __shfl_xor_sync(0xFFFFFFFFu, bv, o);
        if (lane == 0) {
            g_part[blockIdx.x] = bv;
            __threadfence();
            unsigned int t = atomicAdd(&g_ticket, 1u);
            s_last = (t == (unsigned int)(BLOCKS - 1));
        }
    }
    __syncthreads();

    // ---- last block sums all partials and writes the scalar ----
    if (s_last) {
        double acc = 0.0;
        for (int i = threadIdx.x; i < BLOCKS; i += THREADS) acc += (double)g_part[i];
        // reduce doubles via float path is lossy; shuffle doubles instead
#pragma unroll
        for (int o = 16; o > 0; o >>= 1)
            acc += __shfl_xor_sync(0xFFFFFFFFu, acc, o);
        __shared__ double warp_d[THREADS / 32];
        if (lane == 0) warp_d[wid] = acc;
        __syncthreads();
        if (wid == 0) {
            double bd = (lane < (THREADS / 32)) ? warp_d[lane] : 0.0;
#pragma unroll
            for (int o = 4; o > 0; o >>= 1)
                bd += __shfl_xor_sync(0xFFFFFFFFu, bd, o);
            if (lane == 0) {
                out[0] = (float)(bd / (double)NLOC);
                __threadfence();
                g_ticket = 0;  // reset for next graph replay (deterministic)
            }
        }
    }
}

extern "C" void kernel_launch(void* const* d_in, const int* in_sizes, int n_in,
                              void* d_out, int out_size) {
    const float* a = (const float*)d_in[0];
    const float* b = (const float*)d_in[1];
    const float* target = a;
    const float* pred = b;
    if (n_in >= 2 && in_sizes[0] > in_sizes[1]) {
        target = b;
        pred = a;
    }
    crps_kernel<<<BLOCKS, THREADS>>>((const float4*)target, (const float4*)pred,
                                     (float*)d_out);
}